// round 3
// baseline (speedup 1.0000x reference)
#include <cuda_runtime.h>

#define GRID_S 224
#define DIM 512
#define CELLS (GRID_S * GRID_S)

// Scratch (no device allocations allowed) — cell -> token index map and
// channel-major transposed weights.
__device__ int   g_map[CELLS];
__device__ float g_wt[9 * DIM];

__global__ void init_map_kernel() {
    int i = blockIdx.x * blockDim.x + threadIdx.x;
    if (i < CELLS) g_map[i] = -1;
}

__global__ void scatter_map_kernel(const int* __restrict__ pos, int n) {
    int i = blockIdx.x * blockDim.x + threadIdx.x;
    if (i < n) {
        int r = pos[2 * i];
        int c = pos[2 * i + 1];
        g_map[r * GRID_S + c] = i;
    }
}

// w is [DIM][1][3][3] row-major -> g_wt[k][c] with k = kh*3+kw.
__global__ void transpose_w_kernel(const float* __restrict__ w) {
    int i = blockIdx.x * blockDim.x + threadIdx.x;
    if (i < 9 * DIM) {
        int c = i / 9;
        int k = i % 9;
        g_wt[k * DIM + c] = w[i];
    }
}

// One block per token. 128 threads x float4 = 512 channels.
// out[n,c] = x[n,c] + (mask ? b[c] + sum_k w_t[k,c] * x[nbr_k, c] : 0)
// where nbr_k for k = kh*3+kw lives at raw cell (p0 + kw - 1, p1 + kh - 1)
// (kh indexes the column axis, kw the row axis, due to the reference's
// transpose(2,1,0) before/after the NCHW conv).
__global__ __launch_bounds__(128) void sparse_dwconv_kernel(
    const float* __restrict__ x,
    const int*   __restrict__ pos,
    const float* __restrict__ b,
    float*       __restrict__ out)
{
    const int tok = blockIdx.x;
    const int tid = threadIdx.x;

    __shared__ int   s_nbr[9];
    __shared__ float s_wsum[4];

    const int p0 = pos[2 * tok];
    const int p1 = pos[2 * tok + 1];

    if (tid < 9) {
        const int kh = tid / 3;
        const int kw = tid % 3;
        const int r = p0 + kw - 1;   // row axis moves with kw
        const int c = p1 + kh - 1;   // col axis moves with kh
        int idx = -1;
        if (r >= 0 && r < GRID_S && c >= 0 && c < GRID_S)
            idx = g_map[r * GRID_S + c];
        s_nbr[tid] = idx;
    }
    __syncthreads();

    const int base = tid * 4;
    const float4 xc = *reinterpret_cast<const float4*>(x + (size_t)tok * DIM + base);

    float4 acc = make_float4(0.f, 0.f, 0.f, 0.f);
#pragma unroll
    for (int k = 0; k < 9; ++k) {
        const int nb = s_nbr[k];
        if (nb >= 0) {
            const float4 xv = *reinterpret_cast<const float4*>(x + (size_t)nb * DIM + base);
            const float4 wv = *reinterpret_cast<const float4*>(g_wt + k * DIM + base);
            acc.x = fmaf(wv.x, xv.x, acc.x);
            acc.y = fmaf(wv.y, xv.y, acc.y);
            acc.z = fmaf(wv.z, xv.z, acc.z);
            acc.w = fmaf(wv.w, xv.w, acc.w);
        }
    }

    // Mask: channel-sum of this token's features (block reduction over 512 ch).
    float s = xc.x + xc.y + xc.z + xc.w;
#pragma unroll
    for (int o = 16; o > 0; o >>= 1)
        s += __shfl_xor_sync(0xffffffffu, s, o);
    if ((tid & 31) == 0) s_wsum[tid >> 5] = s;
    __syncthreads();
    const float total = s_wsum[0] + s_wsum[1] + s_wsum[2] + s_wsum[3];

    float4 o4;
    if (total != 0.0f) {
        const float4 bv = *reinterpret_cast<const float4*>(b + base);
        o4.x = xc.x + acc.x + bv.x;
        o4.y = xc.y + acc.y + bv.y;
        o4.z = xc.z + acc.z + bv.z;
        o4.w = xc.w + acc.w + bv.w;
    } else {
        o4 = xc;  // masked cell: conv (incl. bias) zeroed, residual only
    }
    *reinterpret_cast<float4*>(out + (size_t)tok * DIM + base) = o4;
}

extern "C" void kernel_launch(void* const* d_in, const int* in_sizes, int n_in,
                              void* d_out, int out_size) {
    const float* x   = (const float*)d_in[0];   // [1, N, 512]
    const int*   pos = (const int*)  d_in[1];   // [N, 2]
    const float* w   = (const float*)d_in[2];   // [512, 1, 3, 3]
    const float* b   = (const float*)d_in[3];   // [512]
    float* out = (float*)d_out;                 // [1, N, 512]

    const int n = in_sizes[1] / 2;

    init_map_kernel<<<(CELLS + 255) / 256, 256>>>();
    scatter_map_kernel<<<(n + 255) / 256, 256>>>(pos, n);
    transpose_w_kernel<<<(9 * DIM + 255) / 256, 256>>>(w);
    sparse_dwconv_kernel<<<n, 128>>>(x, pos, b, out);
}

// round 4
// speedup vs baseline: 1.1250x; 1.1250x over previous
#include <cuda_runtime.h>

#define GRID_S 224
#define DIM 512
#define CELLS (GRID_S * GRID_S)
#define TPB 8   // tokens per block

// Scratch (no device allocations allowed)
__device__ int   g_map[CELLS];
__device__ float g_wt[9 * DIM];

// Fused: init map to -1 AND transpose w [DIM][3][3] -> g_wt[k][c]
__global__ void init_and_transpose_kernel(const float* __restrict__ w) {
    int i = blockIdx.x * blockDim.x + threadIdx.x;
    if (i < CELLS) g_map[i] = -1;
    if (i < 9 * DIM) {
        int c = i / 9;
        int k = i % 9;
        g_wt[k * DIM + c] = w[i];
    }
}

__global__ void scatter_map_kernel(const int* __restrict__ pos, int n) {
    int i = blockIdx.x * blockDim.x + threadIdx.x;
    if (i < n) {
        int r = pos[2 * i];
        int c = pos[2 * i + 1];
        g_map[r * GRID_S + c] = i;
    }
}

// One block per TPB tokens. 128 threads x float4 = 512 channels.
// Weights + bias are hoisted into registers once per block and reused
// across the TPB tokens (cuts the dominant L1 traffic term).
__global__ __launch_bounds__(128) void sparse_dwconv_kernel(
    const float* __restrict__ x,
    const int*   __restrict__ pos,
    const float* __restrict__ b,
    float*       __restrict__ out,
    int n)
{
    const int tok0 = blockIdx.x * TPB;
    const int tid = threadIdx.x;

    __shared__ int   s_nbr[TPB][9];
    __shared__ float s_wsum[2][4];   // parity double-buffer for mask reduce

    // Preamble: neighbor lookups for all TPB tokens (72 threads).
    if (tid < TPB * 9) {
        const int t = tid / 9;
        const int k = tid % 9;
        const int tok = tok0 + t;
        int idx = -1;
        if (tok < n) {
            const int p0 = pos[2 * tok];
            const int p1 = pos[2 * tok + 1];
            const int kh = k / 3;
            const int kw = k % 3;
            const int r = p0 + kw - 1;   // row axis moves with kw
            const int c = p1 + kh - 1;   // col axis moves with kh
            if (r >= 0 && r < GRID_S && c >= 0 && c < GRID_S)
                idx = g_map[r * GRID_S + c];
        }
        s_nbr[t][k] = idx;
    }

    const int base = tid * 4;

    // Hoist weights (9 x float4 = 36 regs) and bias once per block.
    float4 wreg[9];
#pragma unroll
    for (int k = 0; k < 9; ++k)
        wreg[k] = *reinterpret_cast<const float4*>(g_wt + k * DIM + base);
    const float4 bv = *reinterpret_cast<const float4*>(b + base);

    __syncthreads();

#pragma unroll
    for (int t = 0; t < TPB; ++t) {
        const int tok = tok0 + t;
        if (tok >= n) break;

        const float4 xc = *reinterpret_cast<const float4*>(
            x + (size_t)tok * DIM + base);

        float4 acc = make_float4(0.f, 0.f, 0.f, 0.f);
#pragma unroll
        for (int k = 0; k < 9; ++k) {
            const int nb = s_nbr[t][k];
            if (nb >= 0) {
                const float4 xv = *reinterpret_cast<const float4*>(
                    x + (size_t)nb * DIM + base);
                acc.x = fmaf(wreg[k].x, xv.x, acc.x);
                acc.y = fmaf(wreg[k].y, xv.y, acc.y);
                acc.z = fmaf(wreg[k].z, xv.z, acc.z);
                acc.w = fmaf(wreg[k].w, xv.w, acc.w);
            }
        }

        // Mask: channel-sum of this token's features over all 512 channels.
        float s = xc.x + xc.y + xc.z + xc.w;
#pragma unroll
        for (int o = 16; o > 0; o >>= 1)
            s += __shfl_xor_sync(0xffffffffu, s, o);
        if ((tid & 31) == 0) s_wsum[t & 1][tid >> 5] = s;
        __syncthreads();
        const float total = s_wsum[t & 1][0] + s_wsum[t & 1][1]
                          + s_wsum[t & 1][2] + s_wsum[t & 1][3];

        float4 o4;
        if (total != 0.0f) {
            o4.x = xc.x + acc.x + bv.x;
            o4.y = xc.y + acc.y + bv.y;
            o4.z = xc.z + acc.z + bv.z;
            o4.w = xc.w + acc.w + bv.w;
        } else {
            o4 = xc;  // masked cell: conv (incl. bias) zeroed, residual only
        }
        *reinterpret_cast<float4*>(out + (size_t)tok * DIM + base) = o4;
    }
}

extern "C" void kernel_launch(void* const* d_in, const int* in_sizes, int n_in,
                              void* d_out, int out_size) {
    const float* x   = (const float*)d_in[0];   // [1, N, 512]
    const int*   pos = (const int*)  d_in[1];   // [N, 2]
    const float* w   = (const float*)d_in[2];   // [512, 1, 3, 3]
    const float* b   = (const float*)d_in[3];   // [512]
    float* out = (float*)d_out;                 // [1, N, 512]

    const int n = in_sizes[1] / 2;

    init_and_transpose_kernel<<<(CELLS + 255) / 256, 256>>>(w);
    scatter_map_kernel<<<(n + 255) / 256, 256>>>(pos, n);
    sparse_dwconv_kernel<<<(n + TPB - 1) / TPB, 128>>>(x, pos, b, out, n);
}

// round 5
// speedup vs baseline: 1.1672x; 1.0375x over previous
#include <cuda_runtime.h>

#define GRID_S 224
#define DIM 512
#define CELLS (GRID_S * GRID_S)
#define TPB 8   // tokens per block

// Scratch (no device allocations allowed).
// g_map is NEVER cleared: lookups are validated against pos, so stale
// contents (zero-init on first call, previous identical scatter after)
// cannot affect the result -> deterministic without an init pass.
__device__ int   g_map[CELLS];
__device__ float g_wt[9 * DIM];

// Fused prep: scatter cell->token map AND transpose w [DIM][3][3] -> g_wt[k][c]
__global__ void prep_kernel(const int* __restrict__ pos,
                            const float* __restrict__ w, int n) {
    int i = blockIdx.x * blockDim.x + threadIdx.x;
    if (i < n) {
        int r = pos[2 * i];
        int c = pos[2 * i + 1];
        g_map[r * GRID_S + c] = i;
    }
    if (i < 9 * DIM) {
        int c = i / 9;
        int k = i % 9;
        g_wt[k * DIM + c] = w[i];
    }
}

// One block per TPB tokens. 128 threads x float4 = 512 channels.
// Weights + bias hoisted into registers once per block; the center tap
// (k=4) is the token itself, so its row is reused from the residual load.
__global__ __launch_bounds__(128) void sparse_dwconv_kernel(
    const float* __restrict__ x,
    const int*   __restrict__ pos,
    const float* __restrict__ b,
    float*       __restrict__ out,
    int n)
{
    const int tok0 = blockIdx.x * TPB;
    const int tid = threadIdx.x;

    __shared__ int   s_nbr[TPB][9];   // [t][k], k=4 unused (center = self)
    __shared__ float s_wsum[2][4];    // parity double-buffer for mask reduce

    // Preamble: validated neighbor lookups for all TPB tokens (72 threads).
    if (tid < TPB * 9) {
        const int t = tid / 9;
        const int k = tid % 9;
        const int tok = tok0 + t;
        int idx = -1;
        if (tok < n && k != 4) {
            const int p0 = pos[2 * tok];
            const int p1 = pos[2 * tok + 1];
            const int kh = k / 3;
            const int kw = k % 3;
            const int r = p0 + kw - 1;   // row axis moves with kw
            const int c = p1 + kh - 1;   // col axis moves with kh
            if (r >= 0 && r < GRID_S && c >= 0 && c < GRID_S) {
                int cand = g_map[r * GRID_S + c];
                // validate against pos: stale/zero map contents rejected
                if ((unsigned)cand < (unsigned)n &&
                    pos[2 * cand] == r && pos[2 * cand + 1] == c)
                    idx = cand;
            }
        }
        s_nbr[t][k] = idx;
    }

    const int base = tid * 4;

    // Hoist weights (9 x float4 = 36 regs) and bias once per block.
    float4 wreg[9];
#pragma unroll
    for (int k = 0; k < 9; ++k)
        wreg[k] = *reinterpret_cast<const float4*>(g_wt + k * DIM + base);
    const float4 bv = *reinterpret_cast<const float4*>(b + base);

    __syncthreads();

#pragma unroll
    for (int t = 0; t < TPB; ++t) {
        const int tok = tok0 + t;
        if (tok >= n) break;

        const float4 xc = *reinterpret_cast<const float4*>(
            x + (size_t)tok * DIM + base);

        // Center tap: always the token itself (its cell is occupied by it).
        float4 acc;
        acc.x = wreg[4].x * xc.x;
        acc.y = wreg[4].y * xc.y;
        acc.z = wreg[4].z * xc.z;
        acc.w = wreg[4].w * xc.w;

#pragma unroll
        for (int k = 0; k < 9; ++k) {
            if (k == 4) continue;
            const int nb = s_nbr[t][k];
            if (nb >= 0) {
                const float4 xv = *reinterpret_cast<const float4*>(
                    x + (size_t)nb * DIM + base);
                acc.x = fmaf(wreg[k].x, xv.x, acc.x);
                acc.y = fmaf(wreg[k].y, xv.y, acc.y);
                acc.z = fmaf(wreg[k].z, xv.z, acc.z);
                acc.w = fmaf(wreg[k].w, xv.w, acc.w);
            }
        }

        // Mask: channel-sum of this token's features over all 512 channels.
        float s = xc.x + xc.y + xc.z + xc.w;
#pragma unroll
        for (int o = 16; o > 0; o >>= 1)
            s += __shfl_xor_sync(0xffffffffu, s, o);
        if ((tid & 31) == 0) s_wsum[t & 1][tid >> 5] = s;
        __syncthreads();
        const float total = s_wsum[t & 1][0] + s_wsum[t & 1][1]
                          + s_wsum[t & 1][2] + s_wsum[t & 1][3];

        float4 o4;
        if (total != 0.0f) {
            o4.x = xc.x + acc.x + bv.x;
            o4.y = xc.y + acc.y + bv.y;
            o4.z = xc.z + acc.z + bv.z;
            o4.w = xc.w + acc.w + bv.w;
        } else {
            o4 = xc;  // masked cell: conv (incl. bias) zeroed, residual only
        }
        *reinterpret_cast<float4*>(out + (size_t)tok * DIM + base) = o4;
    }
}

extern "C" void kernel_launch(void* const* d_in, const int* in_sizes, int n_in,
                              void* d_out, int out_size) {
    const float* x   = (const float*)d_in[0];   // [1, N, 512]
    const int*   pos = (const int*)  d_in[1];   // [N, 2]
    const float* w   = (const float*)d_in[2];   // [512, 1, 3, 3]
    const float* b   = (const float*)d_in[3];   // [512]
    float* out = (float*)d_out;                 // [1, N, 512]

    const int n = in_sizes[1] / 2;

    const int prep_elems = (n > 9 * DIM) ? n : 9 * DIM;
    prep_kernel<<<(prep_elems + 255) / 256, 256>>>(pos, w, n);
    sparse_dwconv_kernel<<<(n + TPB - 1) / TPB, 128>>>(x, pos, b, out, n);
}